// round 1
// baseline (speedup 1.0000x reference)
#include <cuda_runtime.h>
#include <cstdint>
#include <cstddef>

// ---------------------------------------------------------------------------
// Block-sparse linear: y[N,OUT] = x[N,IN] @ W^T + bias
// W has K dense 64x64 tiles; tile k sits at block-grid (row_idx[k], col_idx[k]).
// y[m, r*64+n] += sum_i x[m, c*64+i] * blocks[k, n, i]
//
// Strategy (round 0): group blocks by output row-group, then per-CTA gather-GEMM
// with tf32 mma.sync.m16n8k8 (explicit cvt.rna for unbiased ~4e-4 error).
// CTA tile: 128 rows x 64 out-cols, 8 warps as 4(M) x 2(N).
// ---------------------------------------------------------------------------

#define BS 64
#define MAX_GROUPS 64
#define MAX_BLKS 1024
#define XSTRIDE 68   // 68 mod 32 = 4 -> conflict-free A-fragment LDS
#define BSTRIDE 68

__device__ int g_list[MAX_GROUPS * MAX_BLKS];
__device__ int g_count[MAX_GROUPS];

// Deterministic per-row-group block lists via warp ballot (one warp per group).
__global__ void build_lists_kernel(const int* __restrict__ row_idx, int K) {
    int r = blockIdx.x;
    int lane = threadIdx.x;
    int cnt = 0;
    for (int base = 0; base < K; base += 32) {
        int k = base + lane;
        int v = (k < K) ? row_idx[k] : -1;
        unsigned m = __ballot_sync(0xffffffffu, v == r);
        if (v == r) {
            int pos = cnt + __popc(m & ((1u << lane) - 1u));
            g_list[r * MAX_BLKS + pos] = k;
        }
        cnt += __popc(m);
    }
    if (lane == 0) g_count[r] = cnt;
}

__device__ __forceinline__ uint32_t f2tf(float f) {
    uint32_t r;
    asm("cvt.rna.tf32.f32 %0, %1;" : "=r"(r) : "f"(f));
    return r;
}

__global__ __launch_bounds__(256, 2)
void bs_linear_kernel(const float* __restrict__ x,
                      const float* __restrict__ blocks,
                      const float* __restrict__ bias,
                      const int* __restrict__ col_idx,
                      float* __restrict__ y,
                      int IN, int OUT)
{
    extern __shared__ uint32_t smem[];
    uint32_t* Xs  = smem;                   // [128][XSTRIDE] tf32 bits
    uint32_t* Bsm = smem + 128 * XSTRIDE;   // [64][BSTRIDE]  tf32 bits (blk[n][k])

    const int m0   = blockIdx.x * 128;
    const int r    = blockIdx.y;
    const int tid  = threadIdx.x;
    const int lane = tid & 31;
    const int warp = tid >> 5;
    const int warp_m = warp >> 1;   // 0..3  (32 rows each)
    const int warp_n = warp & 1;    // 0..1  (32 cols each)

    float acc[2][4][4];
    #pragma unroll
    for (int mi = 0; mi < 2; mi++)
        #pragma unroll
        for (int ni = 0; ni < 4; ni++)
            #pragma unroll
            for (int j = 0; j < 4; j++) acc[mi][ni][j] = 0.0f;

    const int cnt = g_count[r];

    // X load mapping: 256 threads = 128 rows x 2 halves, 8 float4 each
    const int xrow     = tid >> 1;
    const int xcolbase = (tid & 1) * 32;
    // B load mapping: 256 threads = 64 rows x 4 quarters, 4 float4 each
    const int brow     = tid >> 2;
    const int bcolbase = (tid & 3) * 16;

    for (int it = 0; it < cnt; ++it) {
        const int blk = g_list[r * MAX_BLKS + it];
        const int c   = col_idx[blk];

        __syncthreads();  // previous iteration's MMAs done reading SMEM

        // Load + rna-round X tile [128 x 64]
        const float4* xg = reinterpret_cast<const float4*>(
            x + (size_t)(m0 + xrow) * IN + (size_t)c * BS + xcolbase);
        #pragma unroll
        for (int i = 0; i < 8; ++i) {
            float4 v = xg[i];
            uint32_t* d = &Xs[xrow * XSTRIDE + xcolbase + i * 4];
            d[0] = f2tf(v.x); d[1] = f2tf(v.y); d[2] = f2tf(v.z); d[3] = f2tf(v.w);
        }
        // Load + rna-round B tile [64 n x 64 k], row-major n, contiguous k
        const float4* bg = reinterpret_cast<const float4*>(
            blocks + (size_t)blk * BS * BS + (size_t)brow * BS + bcolbase);
        #pragma unroll
        for (int i = 0; i < 4; ++i) {
            float4 v = bg[i];
            uint32_t* d = &Bsm[brow * BSTRIDE + bcolbase + i * 4];
            d[0] = f2tf(v.x); d[1] = f2tf(v.y); d[2] = f2tf(v.z); d[3] = f2tf(v.w);
        }
        __syncthreads();

        #pragma unroll
        for (int k0 = 0; k0 < BS; k0 += 8) {
            uint32_t afrag[2][4];
            uint32_t bfrag[4][2];
            const int cc = k0 + (lane & 3);
            #pragma unroll
            for (int mi = 0; mi < 2; mi++) {
                const int rb = warp_m * 32 + mi * 16 + (lane >> 2);
                afrag[mi][0] = Xs[rb * XSTRIDE + cc];
                afrag[mi][1] = Xs[(rb + 8) * XSTRIDE + cc];
                afrag[mi][2] = Xs[rb * XSTRIDE + cc + 4];
                afrag[mi][3] = Xs[(rb + 8) * XSTRIDE + cc + 4];
            }
            #pragma unroll
            for (int ni = 0; ni < 4; ni++) {
                const int nb = warp_n * 32 + ni * 8 + (lane >> 2);
                bfrag[ni][0] = Bsm[nb * BSTRIDE + cc];
                bfrag[ni][1] = Bsm[nb * BSTRIDE + cc + 4];
            }
            #pragma unroll
            for (int mi = 0; mi < 2; mi++)
                #pragma unroll
                for (int ni = 0; ni < 4; ni++)
                    asm volatile(
                        "mma.sync.aligned.m16n8k8.row.col.f32.tf32.tf32.f32 "
                        "{%0,%1,%2,%3}, {%4,%5,%6,%7}, {%8,%9}, {%0,%1,%2,%3};\n"
                        : "+f"(acc[mi][ni][0]), "+f"(acc[mi][ni][1]),
                          "+f"(acc[mi][ni][2]), "+f"(acc[mi][ni][3])
                        : "r"(afrag[mi][0]), "r"(afrag[mi][1]),
                          "r"(afrag[mi][2]), "r"(afrag[mi][3]),
                          "r"(bfrag[ni][0]), "r"(bfrag[ni][1]));
        }
    }

    // Epilogue: add bias, write fp32 output (always runs: empty groups -> bias only)
    #pragma unroll
    for (int ni = 0; ni < 4; ni++) {
        const int colg = r * BS + warp_n * 32 + ni * 8 + (lane & 3) * 2;
        const float2 bv = *reinterpret_cast<const float2*>(bias + colg);
        #pragma unroll
        for (int mi = 0; mi < 2; mi++) {
            const int rowg = m0 + warp_m * 32 + mi * 16 + (lane >> 2);
            float2 o0 = make_float2(acc[mi][ni][0] + bv.x, acc[mi][ni][1] + bv.y);
            float2 o1 = make_float2(acc[mi][ni][2] + bv.x, acc[mi][ni][3] + bv.y);
            *reinterpret_cast<float2*>(y + (size_t)rowg * OUT + colg) = o0;
            *reinterpret_cast<float2*>(y + (size_t)(rowg + 8) * OUT + colg) = o1;
        }
    }
}

extern "C" void kernel_launch(void* const* d_in, const int* in_sizes, int n_in,
                              void* d_out, int out_size) {
    const float* x      = (const float*)d_in[0];
    const float* blocks = (const float*)d_in[1];
    const float* bias   = (const float*)d_in[2];
    const int* row_idx  = (const int*)d_in[3];
    const int* col_idx  = (const int*)d_in[4];
    float* y = (float*)d_out;

    const int K   = in_sizes[3];
    const int OUT = in_sizes[2];
    const int N   = out_size / OUT;
    const int IN  = in_sizes[0] / N;
    const int out_blocks = OUT / BS;

    build_lists_kernel<<<out_blocks, 32>>>(row_idx, K);

    const int smem_bytes = (128 * XSTRIDE + 64 * BSTRIDE) * 4;  // 52224 B
    cudaFuncSetAttribute(bs_linear_kernel,
                         cudaFuncAttributeMaxDynamicSharedMemorySize, smem_bytes);

    dim3 grid(N / 128, out_blocks);
    bs_linear_kernel<<<grid, 256, smem_bytes>>>(x, blocks, bias, col_idx, y, IN, OUT);
}

// round 3
// speedup vs baseline: 2.3229x; 2.3229x over previous
#include <cuda_runtime.h>
#include <cstdint>
#include <cstddef>

// ---------------------------------------------------------------------------
// Block-sparse linear y = x @ W^T + bias, tf32 mma.sync, ZERO-SMEM main loop.
//
// Pre-pass kernels (per launch, graph-captured, deterministic):
//   pack_x: X[4096,4096] -> g_xp in A-fragment order (rna->tf32 rounded):
//           word4 idx = ((cb*MT + mt)*8 + kc)*32 + lane, the 4 words being
//           X[mt*16+(lane>>2) + {0,8}][cb*64 + kc*8 + (lane&3) + {0,4}]
//   pack_b: blocks[K,64,64] -> g_bp in B-fragment order:
//           word4 idx = ((blk*8 + kc)*4 + ncp)*32 + lane, words =
//           B[ncp*16+(lane>>2) + {0,0,8,8}][kc*8+(lane&3) + {0,4,0,4}]
// Main kernel: CTA = 256 thr (8 warps), tile 256 rows x 64 cols (one group).
// Each warp owns 32 rows; fragments loaded straight from gmem with LDG.128
// (fully coalesced); accumulate in registers; no SMEM, no __syncthreads.
// ---------------------------------------------------------------------------

#define BS 64
#define MAX_GROUPS 64
#define MAX_BLKS 1024

__device__ int g_list[MAX_GROUPS * MAX_BLKS];
__device__ int g_count[MAX_GROUPS];
__device__ float g_xp[(size_t)4096 * 4096];   // 64 MB fragment-packed X (tf32 bits)
__device__ float g_bp[(size_t)MAX_BLKS * 64 * 64]; // 16 MB fragment-packed blocks

__device__ __forceinline__ uint32_t f2tf(float f) {
    uint32_t r;
    asm("cvt.rna.tf32.f32 %0, %1;" : "=r"(r) : "f"(f));
    return r;
}

// ------------------------- list builder -------------------------
__global__ void build_lists_kernel(const int* __restrict__ row_idx, int K) {
    int r = blockIdx.x;
    int lane = threadIdx.x;
    int cnt = 0;
    for (int base = 0; base < K; base += 32) {
        int k = base + lane;
        int v = (k < K) ? row_idx[k] : -1;
        unsigned m = __ballot_sync(0xffffffffu, v == r);
        if (v == r) g_list[r * MAX_BLKS + cnt + __popc(m & ((1u << lane) - 1u))] = k;
        cnt += __popc(m);
    }
    if (lane == 0) g_count[r] = cnt;
}

// ------------------------- pre-pack kernels -------------------------
__global__ void pack_x_kernel(const float* __restrict__ x, int IN, int MT) {
    const size_t idx = (size_t)blockIdx.x * blockDim.x + threadIdx.x;  // float4 units
    const int lane = (int)(idx & 31);
    size_t t = idx >> 5;
    const int kc = (int)(t & 7); t >>= 3;
    const int mt = (int)(t % MT);
    const int cb = (int)(t / MT);

    const int r0 = mt * 16 + (lane >> 2);
    const int c0 = cb * 64 + kc * 8 + (lane & 3);
    const size_t row0 = (size_t)r0 * IN;
    const size_t row8 = row0 + (size_t)8 * IN;

    uint4 v;
    v.x = f2tf(__ldg(x + row0 + c0));
    v.y = f2tf(__ldg(x + row8 + c0));
    v.z = f2tf(__ldg(x + row0 + c0 + 4));
    v.w = f2tf(__ldg(x + row8 + c0 + 4));
    reinterpret_cast<uint4*>(g_xp)[idx] = v;
}

__global__ void pack_b_kernel(const float* __restrict__ blocks) {
    const size_t idx = (size_t)blockIdx.x * blockDim.x + threadIdx.x;  // float4 units
    const int lane = (int)(idx & 31);
    const int ncp = (int)((idx >> 5) & 3);
    const int kc = (int)((idx >> 7) & 7);
    const int blk = (int)(idx >> 10);

    const int n0 = ncp * 16 + (lane >> 2);
    const int k0 = kc * 8 + (lane & 3);
    const float* b = blocks + (size_t)blk * (BS * BS);

    uint4 v;
    v.x = f2tf(__ldg(b + n0 * BS + k0));
    v.y = f2tf(__ldg(b + n0 * BS + k0 + 4));
    v.z = f2tf(__ldg(b + (n0 + 8) * BS + k0));
    v.w = f2tf(__ldg(b + (n0 + 8) * BS + k0 + 4));
    reinterpret_cast<uint4*>(g_bp)[idx] = v;
}

// ------------------------- main GEMM kernel -------------------------
__global__ __launch_bounds__(256, 2)
void bs_mma_kernel(const float* __restrict__ bias,
                   const int* __restrict__ col_idx,
                   float* __restrict__ y,
                   int OUT, int MT)
{
    const int tid = threadIdx.x, lane = tid & 31, warp = tid >> 5;
    const int m0 = blockIdx.x * 256;
    const int r = blockIdx.y;
    const int cnt = g_count[r];

    if (cnt == 0) {  // bias-only rows
        const int row = m0 + tid;
        float4* yr = reinterpret_cast<float4*>(y + (size_t)row * OUT + r * BS);
        const float4* b4 = reinterpret_cast<const float4*>(bias + r * BS);
        #pragma unroll
        for (int i = 0; i < 16; i++) yr[i] = b4[i];
        return;
    }

    const int mtb = (m0 >> 4) + warp * 2;   // this warp's first m-tile
    const uint4* __restrict__ xp4 = reinterpret_cast<const uint4*>(g_xp);
    const uint4* __restrict__ bp4 = reinterpret_cast<const uint4*>(g_bp);

    float acc[2][8][4];
    #pragma unroll
    for (int mi = 0; mi < 2; mi++)
        #pragma unroll
        for (int nt = 0; nt < 8; nt++)
            #pragma unroll
            for (int j = 0; j < 4; j++) acc[mi][nt][j] = 0.0f;

    for (int it = 0; it < cnt; ++it) {
        const int blk = g_list[r * MAX_BLKS + it];
        const int c = __ldg(col_idx + blk);

        // float4-unit bases
        const size_t a0base = ((size_t)(c * MT + mtb) * 8) * 32 + lane;
        const size_t a1base = a0base + 8 * 32;
        const size_t bbase  = (size_t)blk * 1024 + lane;

        #pragma unroll
        for (int kc = 0; kc < 8; kc++) {
            const uint4 a0 = __ldg(xp4 + a0base + kc * 32);
            const uint4 a1 = __ldg(xp4 + a1base + kc * 32);
            uint4 bb[4];
            #pragma unroll
            for (int ncp = 0; ncp < 4; ncp++)
                bb[ncp] = __ldg(bp4 + bbase + kc * 128 + ncp * 32);

            #pragma unroll
            for (int mi = 0; mi < 2; mi++) {
                const uint4 a = mi ? a1 : a0;
                #pragma unroll
                for (int ncp = 0; ncp < 4; ncp++) {
                    asm volatile(
                        "mma.sync.aligned.m16n8k8.row.col.f32.tf32.tf32.f32 "
                        "{%0,%1,%2,%3}, {%4,%5,%6,%7}, {%8,%9}, {%0,%1,%2,%3};\n"
                        : "+f"(acc[mi][2 * ncp][0]), "+f"(acc[mi][2 * ncp][1]),
                          "+f"(acc[mi][2 * ncp][2]), "+f"(acc[mi][2 * ncp][3])
                        : "r"(a.x), "r"(a.y), "r"(a.z), "r"(a.w),
                          "r"(bb[ncp].x), "r"(bb[ncp].y));
                    asm volatile(
                        "mma.sync.aligned.m16n8k8.row.col.f32.tf32.tf32.f32 "
                        "{%0,%1,%2,%3}, {%4,%5,%6,%7}, {%8,%9}, {%0,%1,%2,%3};\n"
                        : "+f"(acc[mi][2 * ncp + 1][0]), "+f"(acc[mi][2 * ncp + 1][1]),
                          "+f"(acc[mi][2 * ncp + 1][2]), "+f"(acc[mi][2 * ncp + 1][3])
                        : "r"(a.x), "r"(a.y), "r"(a.z), "r"(a.w),
                          "r"(bb[ncp].z), "r"(bb[ncp].w));
                }
            }
        }
    }

    // epilogue: add bias, direct STG.64 per accumulator pair
    #pragma unroll
    for (int nt = 0; nt < 8; nt++) {
        const int colg = r * BS + nt * 8 + (lane & 3) * 2;
        const float2 bv = *reinterpret_cast<const float2*>(bias + colg);
        #pragma unroll
        for (int mi = 0; mi < 2; mi++) {
            const int rowg = m0 + warp * 32 + mi * 16 + (lane >> 2);
            float2 o0 = make_float2(acc[mi][nt][0] + bv.x, acc[mi][nt][1] + bv.y);
            float2 o1 = make_float2(acc[mi][nt][2] + bv.x, acc[mi][nt][3] + bv.y);
            *reinterpret_cast<float2*>(y + (size_t)rowg * OUT + colg) = o0;
            *reinterpret_cast<float2*>(y + (size_t)(rowg + 8) * OUT + colg) = o1;
        }
    }
}

// ------------------------------ launch glue --------------------------------
extern "C" void kernel_launch(void* const* d_in, const int* in_sizes, int n_in,
                              void* d_out, int out_size) {
    const float* x      = (const float*)d_in[0];
    const float* blocks = (const float*)d_in[1];
    const float* bias   = (const float*)d_in[2];
    const int* row_idx  = (const int*)d_in[3];
    const int* col_idx  = (const int*)d_in[4];
    float* y = (float*)d_out;

    const int K   = in_sizes[3];
    const int OUT = in_sizes[2];
    const int N   = out_size / OUT;
    const int IN  = in_sizes[0] / N;
    const int out_blocks = OUT / BS;
    const int MT  = N / 16;   // m-tiles per column-block in packed X

    build_lists_kernel<<<out_blocks, 32>>>(row_idx, K);

    const size_t xwords4 = (size_t)N * IN / 4;
    pack_x_kernel<<<(unsigned)(xwords4 / 256), 256>>>(x, IN, MT);
    const size_t bwords4 = (size_t)K * BS * BS / 4;
    pack_b_kernel<<<(unsigned)(bwords4 / 256), 256>>>(blocks);

    dim3 grid(N / 256, out_blocks);
    bs_mma_kernel<<<grid, 256>>>(bias, col_idx, y, OUT, MT);
}

// round 7
// speedup vs baseline: 2.4635x; 1.0605x over previous
#include <cuda_runtime.h>
#include <cstdint>
#include <cstddef>

// ---------------------------------------------------------------------------
// Block-sparse linear y = x @ W^T + bias, tf32 mma.sync, zero-SMEM main loop.
//
// R4 change vs R3: the per-iteration index indirection (g_list[it] ->
// col_idx[blk], two dependent L2-latency loads heading every block-iter) is
// fused into one int2 list entry {blk, col} built once, and prefetched one
// iteration ahead so the fragment loads of iteration `it` issue immediately.
//
// Pre-pass kernels:
//   pack_x: X -> g_xp in A-fragment order (rna->tf32 rounded)
//   pack_b: blocks -> g_bp in B-fragment order (rna->tf32 rounded)
// Main kernel: CTA = 256 thr (8 warps), tile 256 rows x 64 cols (one group).
// ---------------------------------------------------------------------------

#define BS 64
#define MAX_GROUPS 64
#define MAX_BLKS 1024

__device__ int2 g_listc[MAX_GROUPS * MAX_BLKS];  // {blk, col} per entry
__device__ int g_count[MAX_GROUPS];
__device__ float g_xp[(size_t)4096 * 4096];          // fragment-packed X (tf32 bits)
__device__ float g_bp[(size_t)MAX_BLKS * 64 * 64];   // fragment-packed blocks

__device__ __forceinline__ uint32_t f2tf(float f) {
    uint32_t r;
    asm("cvt.rna.tf32.f32 %0, %1;" : "=r"(r) : "f"(f));
    return r;
}

// ------------------------- list builder -------------------------
__global__ void build_lists_kernel(const int* __restrict__ row_idx,
                                   const int* __restrict__ col_idx, int K) {
    int r = blockIdx.x;
    int lane = threadIdx.x;
    int cnt = 0;
    for (int base = 0; base < K; base += 32) {
        int k = base + lane;
        int v = (k < K) ? row_idx[k] : -1;
        unsigned m = __ballot_sync(0xffffffffu, v == r);
        if (v == r) {
            int pos = cnt + __popc(m & ((1u << lane) - 1u));
            g_listc[r * MAX_BLKS + pos] = make_int2(k, col_idx[k]);
        }
        cnt += __popc(m);
    }
    if (lane == 0) g_count[r] = cnt;
}

// ------------------------- pre-pack kernels -------------------------
__global__ void pack_x_kernel(const float* __restrict__ x, int IN, int MT) {
    const size_t idx = (size_t)blockIdx.x * blockDim.x + threadIdx.x;  // float4 units
    const int lane = (int)(idx & 31);
    size_t t = idx >> 5;
    const int kc = (int)(t & 7); t >>= 3;
    const int mt = (int)(t % MT);
    const int cb = (int)(t / MT);

    const int r0 = mt * 16 + (lane >> 2);
    const int c0 = cb * 64 + kc * 8 + (lane & 3);
    const size_t row0 = (size_t)r0 * IN;
    const size_t row8 = row0 + (size_t)8 * IN;

    uint4 v;
    v.x = f2tf(__ldg(x + row0 + c0));
    v.y = f2tf(__ldg(x + row8 + c0));
    v.z = f2tf(__ldg(x + row0 + c0 + 4));
    v.w = f2tf(__ldg(x + row8 + c0 + 4));
    reinterpret_cast<uint4*>(g_xp)[idx] = v;
}

__global__ void pack_b_kernel(const float* __restrict__ blocks) {
    const size_t idx = (size_t)blockIdx.x * blockDim.x + threadIdx.x;  // float4 units
    const int lane = (int)(idx & 31);
    const int ncp = (int)((idx >> 5) & 3);
    const int kc = (int)((idx >> 7) & 7);
    const int blk = (int)(idx >> 10);

    const int n0 = ncp * 16 + (lane >> 2);
    const int k0 = kc * 8 + (lane & 3);
    const float* b = blocks + (size_t)blk * (BS * BS);

    uint4 v;
    v.x = f2tf(__ldg(b + n0 * BS + k0));
    v.y = f2tf(__ldg(b + n0 * BS + k0 + 4));
    v.z = f2tf(__ldg(b + (n0 + 8) * BS + k0));
    v.w = f2tf(__ldg(b + (n0 + 8) * BS + k0 + 4));
    reinterpret_cast<uint4*>(g_bp)[idx] = v;
}

// ------------------------- main GEMM kernel -------------------------
__global__ __launch_bounds__(256, 2)
void bs_mma_kernel(const float* __restrict__ bias,
                   float* __restrict__ y,
                   int OUT, int MT)
{
    const int tid = threadIdx.x, lane = tid & 31, warp = tid >> 5;
    const int m0 = blockIdx.x * 256;
    const int r = blockIdx.y;
    const int cnt = g_count[r];

    if (cnt == 0) {  // bias-only rows
        const int row = m0 + tid;
        float4* yr = reinterpret_cast<float4*>(y + (size_t)row * OUT + r * BS);
        const float4* b4 = reinterpret_cast<const float4*>(bias + r * BS);
        #pragma unroll
        for (int i = 0; i < 16; i++) yr[i] = b4[i];
        return;
    }

    const int mtb = (m0 >> 4) + warp * 2;   // this warp's first m-tile
    const uint4* __restrict__ xp4 = reinterpret_cast<const uint4*>(g_xp);
    const uint4* __restrict__ bp4 = reinterpret_cast<const uint4*>(g_bp);
    const int2* __restrict__ lst = g_listc + r * MAX_BLKS;

    float acc[2][8][4];
    #pragma unroll
    for (int mi = 0; mi < 2; mi++)
        #pragma unroll
        for (int nt = 0; nt < 8; nt++)
            #pragma unroll
            for (int j = 0; j < 4; j++) acc[mi][nt][j] = 0.0f;

    // index prefetch: one iteration ahead
    int2 pc = __ldg(lst);

    for (int it = 0; it < cnt; ++it) {
        const int2 cur = pc;
        if (it + 1 < cnt) pc = __ldg(lst + it + 1);   // overlaps with MMA body

        // float4-unit bases (blk = cur.x, col = cur.y)
        const size_t a0base = ((size_t)(cur.y * MT + mtb) * 8) * 32 + lane;
        const size_t a1base = a0base + 8 * 32;
        const size_t bbase  = (size_t)cur.x * 1024 + lane;

        #pragma unroll
        for (int kc = 0; kc < 8; kc++) {
            const uint4 a0 = __ldg(xp4 + a0base + kc * 32);
            const uint4 a1 = __ldg(xp4 + a1base + kc * 32);
            uint4 bb[4];
            #pragma unroll
            for (int ncp = 0; ncp < 4; ncp++)
                bb[ncp] = __ldg(bp4 + bbase + kc * 128 + ncp * 32);

            #pragma unroll
            for (int mi = 0; mi < 2; mi++) {
                const uint4 a = mi ? a1 : a0;
                #pragma unroll
                for (int ncp = 0; ncp < 4; ncp++) {
                    asm volatile(
                        "mma.sync.aligned.m16n8k8.row.col.f32.tf32.tf32.f32 "
                        "{%0,%1,%2,%3}, {%4,%5,%6,%7}, {%8,%9}, {%0,%1,%2,%3};\n"
                        : "+f"(acc[mi][2 * ncp][0]), "+f"(acc[mi][2 * ncp][1]),
                          "+f"(acc[mi][2 * ncp][2]), "+f"(acc[mi][2 * ncp][3])
                        : "r"(a.x), "r"(a.y), "r"(a.z), "r"(a.w),
                          "r"(bb[ncp].x), "r"(bb[ncp].y));
                    asm volatile(
                        "mma.sync.aligned.m16n8k8.row.col.f32.tf32.tf32.f32 "
                        "{%0,%1,%2,%3}, {%4,%5,%6,%7}, {%8,%9}, {%0,%1,%2,%3};\n"
                        : "+f"(acc[mi][2 * ncp + 1][0]), "+f"(acc[mi][2 * ncp + 1][1]),
                          "+f"(acc[mi][2 * ncp + 1][2]), "+f"(acc[mi][2 * ncp + 1][3])
                        : "r"(a.x), "r"(a.y), "r"(a.z), "r"(a.w),
                          "r"(bb[ncp].z), "r"(bb[ncp].w));
                }
            }
        }
    }

    // epilogue: add bias, direct STG.64 per accumulator pair
    #pragma unroll
    for (int nt = 0; nt < 8; nt++) {
        const int colg = r * BS + nt * 8 + (lane & 3) * 2;
        const float2 bv = *reinterpret_cast<const float2*>(bias + colg);
        #pragma unroll
        for (int mi = 0; mi < 2; mi++) {
            const int rowg = m0 + warp * 32 + mi * 16 + (lane >> 2);
            float2 o0 = make_float2(acc[mi][nt][0] + bv.x, acc[mi][nt][1] + bv.y);
            float2 o1 = make_float2(acc[mi][nt][2] + bv.x, acc[mi][nt][3] + bv.y);
            *reinterpret_cast<float2*>(y + (size_t)rowg * OUT + colg) = o0;
            *reinterpret_cast<float2*>(y + (size_t)(rowg + 8) * OUT + colg) = o1;
        }
    }
}

// ------------------------------ launch glue --------------------------------
extern "C" void kernel_launch(void* const* d_in, const int* in_sizes, int n_in,
                              void* d_out, int out_size) {
    const float* x      = (const float*)d_in[0];
    const float* blocks = (const float*)d_in[1];
    const float* bias   = (const float*)d_in[2];
    const int* row_idx  = (const int*)d_in[3];
    const int* col_idx  = (const int*)d_in[4];
    float* y = (float*)d_out;

    const int K   = in_sizes[3];
    const int OUT = in_sizes[2];
    const int N   = out_size / OUT;
    const int IN  = in_sizes[0] / N;
    const int out_blocks = OUT / BS;
    const int MT  = N / 16;   // m-tiles per column-block in packed X

    build_lists_kernel<<<out_blocks, 32>>>(row_idx, col_idx, K);

    const size_t xwords4 = (size_t)N * IN / 4;
    pack_x_kernel<<<(unsigned)(xwords4 / 256), 256>>>(x, IN, MT);
    const size_t bwords4 = (size_t)K * BS * BS / 4;
    pack_b_kernel<<<(unsigned)(bwords4 / 256), 256>>>(blocks);

    dim3 grid(N / 256, out_blocks);
    bs_mma_kernel<<<grid, 256>>>(bias, y, OUT, MT);
}

// round 8
// speedup vs baseline: 2.5732x; 1.0445x over previous
#include <cuda_runtime.h>
#include <cstdint>
#include <cstddef>

// ---------------------------------------------------------------------------
// Block-sparse linear y = x @ W^T + bias, tf32 mma.sync.
// R8: cp.async (LDGSTS) double-buffered SMEM pipeline at half-iteration
// granularity. Fragment-packed gmem (from pre-pass) means: contiguous cp.async
// source regions, fragment-order SMEM (zero bank conflicts, no swizzle), and
// LDS.128 fragment reads. Latency hiding no longer consumes registers.
// CTA: 256 thr / 8 warps, tile 256 rows x 64 cols (one output block-row group).
// ---------------------------------------------------------------------------

#define BS 64
#define MAX_GROUPS 64
#define MAX_BLKS 1024

#define STAGE_U4 2560                    // 40960 B / 16: A 2048 + B 512 uint4
#define SMEM_BYTES (2 * STAGE_U4 * 16)   // 81920

__device__ int2 g_listc[MAX_GROUPS * MAX_BLKS];  // {blk, col}
__device__ int g_count[MAX_GROUPS];
__device__ float g_xp[(size_t)4096 * 4096];          // fragment-packed X (tf32 bits)
__device__ float g_bp[(size_t)MAX_BLKS * 64 * 64];   // fragment-packed blocks

__device__ __forceinline__ uint32_t f2tf(float f) {
    uint32_t r;
    asm("cvt.rna.tf32.f32 %0, %1;" : "=r"(r) : "f"(f));
    return r;
}

// ------------------------- list builder -------------------------
__global__ void build_lists_kernel(const int* __restrict__ row_idx,
                                   const int* __restrict__ col_idx, int K) {
    int r = blockIdx.x;
    int lane = threadIdx.x;
    int cnt = 0;
    for (int base = 0; base < K; base += 32) {
        int k = base + lane;
        int v = (k < K) ? row_idx[k] : -1;
        unsigned m = __ballot_sync(0xffffffffu, v == r);
        if (v == r) {
            int pos = cnt + __popc(m & ((1u << lane) - 1u));
            g_listc[r * MAX_BLKS + pos] = make_int2(k, col_idx[k]);
        }
        cnt += __popc(m);
    }
    if (lane == 0) g_count[r] = cnt;
}

// ------------------------- pre-pack kernels -------------------------
__global__ void pack_x_kernel(const float* __restrict__ x, int IN, int MT) {
    const size_t idx = (size_t)blockIdx.x * blockDim.x + threadIdx.x;  // float4 units
    const int lane = (int)(idx & 31);
    size_t t = idx >> 5;
    const int kc = (int)(t & 7); t >>= 3;
    const int mt = (int)(t % MT);
    const int cb = (int)(t / MT);

    const int r0 = mt * 16 + (lane >> 2);
    const int c0 = cb * 64 + kc * 8 + (lane & 3);
    const size_t row0 = (size_t)r0 * IN;
    const size_t row8 = row0 + (size_t)8 * IN;

    uint4 v;
    v.x = f2tf(__ldg(x + row0 + c0));
    v.y = f2tf(__ldg(x + row8 + c0));
    v.z = f2tf(__ldg(x + row0 + c0 + 4));
    v.w = f2tf(__ldg(x + row8 + c0 + 4));
    reinterpret_cast<uint4*>(g_xp)[idx] = v;
}

__global__ void pack_b_kernel(const float* __restrict__ blocks) {
    const size_t idx = (size_t)blockIdx.x * blockDim.x + threadIdx.x;  // float4 units
    const int lane = (int)(idx & 31);
    const int ncp = (int)((idx >> 5) & 3);
    const int kc = (int)((idx >> 7) & 7);
    const int blk = (int)(idx >> 10);

    const int n0 = ncp * 16 + (lane >> 2);
    const int k0 = kc * 8 + (lane & 3);
    const float* b = blocks + (size_t)blk * (BS * BS);

    uint4 v;
    v.x = f2tf(__ldg(b + n0 * BS + k0));
    v.y = f2tf(__ldg(b + n0 * BS + k0 + 4));
    v.z = f2tf(__ldg(b + (n0 + 8) * BS + k0));
    v.w = f2tf(__ldg(b + (n0 + 8) * BS + k0 + 4));
    reinterpret_cast<uint4*>(g_bp)[idx] = v;
}

// ------------------------- main GEMM kernel -------------------------
__global__ __launch_bounds__(256, 2)
void bs_mma_kernel(const float* __restrict__ bias,
                   float* __restrict__ y,
                   int OUT, int MT)
{
    extern __shared__ uint4 sm4[];
    const int tid = threadIdx.x, lane = tid & 31, warp = tid >> 5;
    const int m0 = blockIdx.x * 256;
    const int r = blockIdx.y;
    const int cnt = g_count[r];

    if (cnt == 0) {  // bias-only rows
        const int row = m0 + tid;
        float4* yr = reinterpret_cast<float4*>(y + (size_t)row * OUT + r * BS);
        const float4* b4 = reinterpret_cast<const float4*>(bias + r * BS);
        #pragma unroll
        for (int i = 0; i < 16; i++) yr[i] = b4[i];
        return;
    }

    const int mtb_cta = m0 >> 4;   // CTA's first m-tile (16 m-tiles total)
    const uint4* __restrict__ xp4 = reinterpret_cast<const uint4*>(g_xp);
    const uint4* __restrict__ bp4 = reinterpret_cast<const uint4*>(g_bp);
    const int2* __restrict__ lst = g_listc + r * MAX_BLKS;

    float acc[2][8][4];
    #pragma unroll
    for (int mi = 0; mi < 2; mi++)
        #pragma unroll
        for (int nt = 0; nt < 8; nt++)
            #pragma unroll
            for (int j = 0; j < 4; j++) acc[mi][nt][j] = 0.0f;

    // half-stage prefetch: A[16mt x 4kc] 32KB + B[4kc x 64n] 8KB -> buffer
    auto prefetch = [&](int2 e, int half, int bufbase) {
        const uint4* asrc = xp4 + (size_t)(e.y * MT + mtb_cta) * 256 + half * 128;
        #pragma unroll
        for (int t = 0; t < 8; t++) {
            const int i = tid + t * 256;
            const int mt = i >> 7, rest = i & 127;
            uint32_t d = (uint32_t)__cvta_generic_to_shared(sm4 + bufbase + i);
            const uint4* g = asrc + mt * 256 + rest;
            asm volatile("cp.async.cg.shared.global [%0], [%1], 16;" :: "r"(d), "l"(g) : "memory");
        }
        const uint4* bsrc = bp4 + (size_t)e.x * 1024 + half * 512;
        #pragma unroll
        for (int t = 0; t < 2; t++) {
            const int i = tid + t * 256;
            uint32_t d = (uint32_t)__cvta_generic_to_shared(sm4 + bufbase + 2048 + i);
            asm volatile("cp.async.cg.shared.global [%0], [%1], 16;" :: "r"(d), "l"(bsrc + i) : "memory");
        }
        asm volatile("cp.async.commit_group;" ::: "memory");
    };

    const int nstage = cnt * 2;   // 2 half-stages per block
    int2 e0 = __ldg(lst);
    int2 e1 = (cnt > 1) ? __ldg(lst + 1) : e0;

    prefetch(e0, 0, 0);

    for (int s = 0; s < nstage; s++) {
        if (s + 1 < nstage) {
            const int2 pe = ((s + 1) & 1) ? e0 : e1;   // odd stage = 2nd half of same iter
            prefetch(pe, (s + 1) & 1, ((s + 1) & 1) * STAGE_U4);
            asm volatile("cp.async.wait_group 1;" ::: "memory");
        } else {
            asm volatile("cp.async.wait_group 0;" ::: "memory");
        }
        __syncthreads();

        const uint4* bufA = sm4 + (s & 1) * STAGE_U4;
        const uint4* bufB = bufA + 2048;
        const int mtl = warp * 2;

        #pragma unroll
        for (int kcl = 0; kcl < 4; kcl++) {
            const uint4 a0 = bufA[(mtl * 4 + kcl) * 32 + lane];
            const uint4 a1 = bufA[((mtl + 1) * 4 + kcl) * 32 + lane];
            uint4 bb[4];
            #pragma unroll
            for (int ncp = 0; ncp < 4; ncp++)
                bb[ncp] = bufB[(kcl * 4 + ncp) * 32 + lane];

            #pragma unroll
            for (int mi = 0; mi < 2; mi++) {
                const uint4 a = mi ? a1 : a0;
                #pragma unroll
                for (int ncp = 0; ncp < 4; ncp++) {
                    asm volatile(
                        "mma.sync.aligned.m16n8k8.row.col.f32.tf32.tf32.f32 "
                        "{%0,%1,%2,%3}, {%4,%5,%6,%7}, {%8,%9}, {%0,%1,%2,%3};\n"
                        : "+f"(acc[mi][2 * ncp][0]), "+f"(acc[mi][2 * ncp][1]),
                          "+f"(acc[mi][2 * ncp][2]), "+f"(acc[mi][2 * ncp][3])
                        : "r"(a.x), "r"(a.y), "r"(a.z), "r"(a.w),
                          "r"(bb[ncp].x), "r"(bb[ncp].y));
                    asm volatile(
                        "mma.sync.aligned.m16n8k8.row.col.f32.tf32.tf32.f32 "
                        "{%0,%1,%2,%3}, {%4,%5,%6,%7}, {%8,%9}, {%0,%1,%2,%3};\n"
                        : "+f"(acc[mi][2 * ncp + 1][0]), "+f"(acc[mi][2 * ncp + 1][1]),
                          "+f"(acc[mi][2 * ncp + 1][2]), "+f"(acc[mi][2 * ncp + 1][3])
                        : "r"(a.x), "r"(a.y), "r"(a.z), "r"(a.w),
                          "r"(bb[ncp].z), "r"(bb[ncp].w));
                }
            }
        }
        __syncthreads();

        if (s & 1) {   // finished an iteration: slide the index window
            e0 = e1;
            const int nit = (s >> 1) + 2;
            if (nit < cnt) e1 = __ldg(lst + nit);
        }
    }

    // epilogue: add bias, direct STG.64 per accumulator pair
    #pragma unroll
    for (int nt = 0; nt < 8; nt++) {
        const int colg = r * BS + nt * 8 + (lane & 3) * 2;
        const float2 bv = *reinterpret_cast<const float2*>(bias + colg);
        #pragma unroll
        for (int mi = 0; mi < 2; mi++) {
            const int rowg = m0 + warp * 32 + mi * 16 + (lane >> 2);
            float2 o0 = make_float2(acc[mi][nt][0] + bv.x, acc[mi][nt][1] + bv.y);
            float2 o1 = make_float2(acc[mi][nt][2] + bv.x, acc[mi][nt][3] + bv.y);
            *reinterpret_cast<float2*>(y + (size_t)rowg * OUT + colg) = o0;
            *reinterpret_cast<float2*>(y + (size_t)(rowg + 8) * OUT + colg) = o1;
        }
    }
}

// ------------------------------ launch glue --------------------------------
extern "C" void kernel_launch(void* const* d_in, const int* in_sizes, int n_in,
                              void* d_out, int out_size) {
    const float* x      = (const float*)d_in[0];
    const float* blocks = (const float*)d_in[1];
    const float* bias   = (const float*)d_in[2];
    const int* row_idx  = (const int*)d_in[3];
    const int* col_idx  = (const int*)d_in[4];
    float* y = (float*)d_out;

    const int K   = in_sizes[3];
    const int OUT = in_sizes[2];
    const int N   = out_size / OUT;
    const int IN  = in_sizes[0] / N;
    const int out_blocks = OUT / BS;
    const int MT  = N / 16;   // m-tiles per column-block in packed X

    build_lists_kernel<<<out_blocks, 32>>>(row_idx, col_idx, K);

    const size_t xwords4 = (size_t)N * IN / 4;
    pack_x_kernel<<<(unsigned)(xwords4 / 256), 256>>>(x, IN, MT);
    const size_t bwords4 = (size_t)K * BS * BS / 4;
    pack_b_kernel<<<(unsigned)(bwords4 / 256), 256>>>(blocks);

    cudaFuncSetAttribute(bs_mma_kernel,
                         cudaFuncAttributeMaxDynamicSharedMemorySize, SMEM_BYTES);
    dim3 grid(N / 256, out_blocks);
    bs_mma_kernel<<<grid, 256, SMEM_BYTES>>>(bias, y, OUT, MT);
}

// round 9
// speedup vs baseline: 2.8314x; 1.1003x over previous
#include <cuda_runtime.h>
#include <cstdint>
#include <cstddef>

// ---------------------------------------------------------------------------
// Block-sparse linear y = x @ W^T + bias, tf32 mma.sync.
// R9: hybrid operand routing.
//   A (big, L2-resident, warp-private): direct LDG.128 fragment loads with an
//     explicit one-kcl-ahead register double buffer (no SMEM transit at all).
//   B (small, shared by all warps): cp.async into a 4-deep full-iteration SMEM
//     ring (16KB/stage), lookahead-2, wait_group 2, ONE __syncthreads/iter
//     (ring-4 makes the single-sync scheme race-free).
// Crossbar traffic per CTA-iter drops 272KB -> 144KB; syncs 4/iter -> 1/iter.
// CTA: 256 thr / 8 warps, tile 256 rows x 64 cols (one output block-row group).
// ---------------------------------------------------------------------------

#define BS 64
#define MAX_GROUPS 64
#define MAX_BLKS 1024

#define BSTAGE_U4 1024                    // full-iter B: 16KB = 1024 uint4
#define RING 4
#define SMEM_BYTES (RING * BSTAGE_U4 * 16)  // 65536

__device__ int2 g_listc[MAX_GROUPS * MAX_BLKS];  // {blk, col}
__device__ int g_count[MAX_GROUPS];
__device__ float g_xp[(size_t)4096 * 4096];          // fragment-packed X (tf32 bits)
__device__ float g_bp[(size_t)MAX_BLKS * 64 * 64];   // fragment-packed blocks

__device__ __forceinline__ uint32_t f2tf(float f) {
    uint32_t r;
    asm("cvt.rna.tf32.f32 %0, %1;" : "=r"(r) : "f"(f));
    return r;
}

// ------------------------- list builder -------------------------
__global__ void build_lists_kernel(const int* __restrict__ row_idx,
                                   const int* __restrict__ col_idx, int K) {
    int r = blockIdx.x;
    int lane = threadIdx.x;
    int cnt = 0;
    for (int base = 0; base < K; base += 32) {
        int k = base + lane;
        int v = (k < K) ? row_idx[k] : -1;
        unsigned m = __ballot_sync(0xffffffffu, v == r);
        if (v == r) {
            int pos = cnt + __popc(m & ((1u << lane) - 1u));
            g_listc[r * MAX_BLKS + pos] = make_int2(k, col_idx[k]);
        }
        cnt += __popc(m);
    }
    if (lane == 0) g_count[r] = cnt;
}

// ------------------------- pre-pack kernels -------------------------
__global__ void pack_x_kernel(const float* __restrict__ x, int IN, int MT) {
    const size_t idx = (size_t)blockIdx.x * blockDim.x + threadIdx.x;  // float4 units
    const int lane = (int)(idx & 31);
    size_t t = idx >> 5;
    const int kc = (int)(t & 7); t >>= 3;
    const int mt = (int)(t % MT);
    const int cb = (int)(t / MT);

    const int r0 = mt * 16 + (lane >> 2);
    const int c0 = cb * 64 + kc * 8 + (lane & 3);
    const size_t row0 = (size_t)r0 * IN;
    const size_t row8 = row0 + (size_t)8 * IN;

    uint4 v;
    v.x = f2tf(__ldg(x + row0 + c0));
    v.y = f2tf(__ldg(x + row8 + c0));
    v.z = f2tf(__ldg(x + row0 + c0 + 4));
    v.w = f2tf(__ldg(x + row8 + c0 + 4));
    reinterpret_cast<uint4*>(g_xp)[idx] = v;
}

__global__ void pack_b_kernel(const float* __restrict__ blocks) {
    const size_t idx = (size_t)blockIdx.x * blockDim.x + threadIdx.x;  // float4 units
    const int lane = (int)(idx & 31);
    const int ncp = (int)((idx >> 5) & 3);
    const int kc = (int)((idx >> 7) & 7);
    const int blk = (int)(idx >> 10);

    const int n0 = ncp * 16 + (lane >> 2);
    const int k0 = kc * 8 + (lane & 3);
    const float* b = blocks + (size_t)blk * (BS * BS);

    uint4 v;
    v.x = f2tf(__ldg(b + n0 * BS + k0));
    v.y = f2tf(__ldg(b + n0 * BS + k0 + 4));
    v.z = f2tf(__ldg(b + (n0 + 8) * BS + k0));
    v.w = f2tf(__ldg(b + (n0 + 8) * BS + k0 + 4));
    reinterpret_cast<uint4*>(g_bp)[idx] = v;
}

// ------------------------- main GEMM kernel -------------------------
__global__ __launch_bounds__(256, 2)
void bs_mma_kernel(const float* __restrict__ bias,
                   float* __restrict__ y,
                   int OUT, int MT)
{
    extern __shared__ uint4 smB[];
    const int tid = threadIdx.x, lane = tid & 31, warp = tid >> 5;
    const int m0 = blockIdx.x * 256;
    const int r = blockIdx.y;
    const int cnt = g_count[r];

    if (cnt == 0) {  // bias-only rows
        const int row = m0 + tid;
        float4* yr = reinterpret_cast<float4*>(y + (size_t)row * OUT + r * BS);
        const float4* b4 = reinterpret_cast<const float4*>(bias + r * BS);
        #pragma unroll
        for (int i = 0; i < 16; i++) yr[i] = b4[i];
        return;
    }

    const int mtb = (m0 >> 4) + warp * 2;   // warp's first m-tile (of its 2)
    const uint4* __restrict__ xp4 = reinterpret_cast<const uint4*>(g_xp);
    const uint4* __restrict__ bp4 = reinterpret_cast<const uint4*>(g_bp);
    const int2* __restrict__ lst = g_listc + r * MAX_BLKS;

    float acc[2][8][4];
    #pragma unroll
    for (int mi = 0; mi < 2; mi++)
        #pragma unroll
        for (int nt = 0; nt < 8; nt++)
            #pragma unroll
            for (int j = 0; j < 4; j++) acc[mi][nt][j] = 0.0f;

    // B prefetch: full iteration tile (1024 uint4), 4 cp.async per thread
    auto prefetchB = [&](int blk, int buf) {
        const uint4* src = bp4 + (size_t)blk * 1024;
        uint4* dstb = smB + buf * BSTAGE_U4;
        #pragma unroll
        for (int t = 0; t < 4; t++) {
            const int i = tid + t * 256;
            uint32_t d = (uint32_t)__cvta_generic_to_shared(dstb + i);
            asm volatile("cp.async.cg.shared.global [%0], [%1], 16;"
                         :: "r"(d), "l"(src + i) : "memory");
        }
        asm volatile("cp.async.commit_group;" ::: "memory");
    };

    // A fragment address (uint4 units) for (col-block c, m-tile mt, kc)
    auto aoff = [&](int c, int mt, int kc) -> size_t {
        return ((size_t)(c * MT + mt) * 8 + kc) * 32 + lane;
    };

    // prime: index window + two B stages + iter-0 A (kc=0) registers
    int2 e_cur = __ldg(lst);
    int2 e_next = (cnt > 1) ? __ldg(lst + 1) : e_cur;
    prefetchB(e_cur.x, 0);
    if (cnt > 1) prefetchB(e_next.x, 1);

    uint4 ac0 = __ldg(xp4 + aoff(e_cur.y, mtb, 0));
    uint4 ac1 = __ldg(xp4 + aoff(e_cur.y, mtb + 1, 0));

    for (int it = 0; it < cnt; ++it) {
        int2 e2 = e_next;
        if (it + 2 < cnt) {
            e2 = __ldg(lst + it + 2);
            prefetchB(e2.x, (it + 2) & 3);
            asm volatile("cp.async.wait_group 2;" ::: "memory");
        } else if (it + 1 < cnt) {
            asm volatile("cp.async.wait_group 1;" ::: "memory");
        } else {
            asm volatile("cp.async.wait_group 0;" ::: "memory");
        }
        __syncthreads();   // single barrier per iteration (ring-4 makes this safe)

        const uint4* bufB = smB + (it & 3) * BSTAGE_U4;

        #pragma unroll
        for (int kc = 0; kc < 8; kc++) {
            // preload next kcl's A fragments (or next iteration's kc=0)
            uint4 an0, an1;
            if (kc < 7) {
                an0 = __ldg(xp4 + aoff(e_cur.y, mtb, kc + 1));
                an1 = __ldg(xp4 + aoff(e_cur.y, mtb + 1, kc + 1));
            } else {
                an0 = __ldg(xp4 + aoff(e_next.y, mtb, 0));
                an1 = __ldg(xp4 + aoff(e_next.y, mtb + 1, 0));
            }

            uint4 bb[4];
            #pragma unroll
            for (int ncp = 0; ncp < 4; ncp++)
                bb[ncp] = bufB[(kc * 4 + ncp) * 32 + lane];

            #pragma unroll
            for (int mi = 0; mi < 2; mi++) {
                const uint4 a = mi ? ac1 : ac0;
                #pragma unroll
                for (int ncp = 0; ncp < 4; ncp++) {
                    asm volatile(
                        "mma.sync.aligned.m16n8k8.row.col.f32.tf32.tf32.f32 "
                        "{%0,%1,%2,%3}, {%4,%5,%6,%7}, {%8,%9}, {%0,%1,%2,%3};\n"
                        : "+f"(acc[mi][2 * ncp][0]), "+f"(acc[mi][2 * ncp][1]),
                          "+f"(acc[mi][2 * ncp][2]), "+f"(acc[mi][2 * ncp][3])
                        : "r"(a.x), "r"(a.y), "r"(a.z), "r"(a.w),
                          "r"(bb[ncp].x), "r"(bb[ncp].y));
                    asm volatile(
                        "mma.sync.aligned.m16n8k8.row.col.f32.tf32.tf32.f32 "
                        "{%0,%1,%2,%3}, {%4,%5,%6,%7}, {%8,%9}, {%0,%1,%2,%3};\n"
                        : "+f"(acc[mi][2 * ncp + 1][0]), "+f"(acc[mi][2 * ncp + 1][1]),
                          "+f"(acc[mi][2 * ncp + 1][2]), "+f"(acc[mi][2 * ncp + 1][3])
                        : "r"(a.x), "r"(a.y), "r"(a.z), "r"(a.w),
                          "r"(bb[ncp].z), "r"(bb[ncp].w));
                }
            }
            ac0 = an0;
            ac1 = an1;
        }

        e_cur = e_next;
        e_next = e2;
    }

    // epilogue: add bias, direct STG.64 per accumulator pair
    #pragma unroll
    for (int nt = 0; nt < 8; nt++) {
        const int colg = r * BS + nt * 8 + (lane & 3) * 2;
        const float2 bv = *reinterpret_cast<const float2*>(bias + colg);
        #pragma unroll
        for (int mi = 0; mi < 2; mi++) {
            const int rowg = m0 + warp * 32 + mi * 16 + (lane >> 2);
            float2 o0 = make_float2(acc[mi][nt][0] + bv.x, acc[mi][nt][1] + bv.y);
            float2 o1 = make_float2(acc[mi][nt][2] + bv.x, acc[mi][nt][3] + bv.y);
            *reinterpret_cast<float2*>(y + (size_t)rowg * OUT + colg) = o0;
            *reinterpret_cast<float2*>(y + (size_t)(rowg + 8) * OUT + colg) = o1;
        }
    }
}

// ------------------------------ launch glue --------------------------------
extern "C" void kernel_launch(void* const* d_in, const int* in_sizes, int n_in,
                              void* d_out, int out_size) {
    const float* x      = (const float*)d_in[0];
    const float* blocks = (const float*)d_in[1];
    const float* bias   = (const float*)d_in[2];
    const int* row_idx  = (const int*)d_in[3];
    const int* col_idx  = (const int*)d_in[4];
    float* y = (float*)d_out;

    const int K   = in_sizes[3];
    const int OUT = in_sizes[2];
    const int N   = out_size / OUT;
    const int IN  = in_sizes[0] / N;
    const int out_blocks = OUT / BS;
    const int MT  = N / 16;   // m-tiles per column-block in packed X

    build_lists_kernel<<<out_blocks, 32>>>(row_idx, col_idx, K);

    const size_t xwords4 = (size_t)N * IN / 4;
    pack_x_kernel<<<(unsigned)(xwords4 / 256), 256>>>(x, IN, MT);
    const size_t bwords4 = (size_t)K * BS * BS / 4;
    pack_b_kernel<<<(unsigned)(bwords4 / 256), 256>>>(blocks);

    cudaFuncSetAttribute(bs_mma_kernel,
                         cudaFuncAttributeMaxDynamicSharedMemorySize, SMEM_BYTES);
    dim3 grid(N / 256, out_blocks);
    bs_mma_kernel<<<grid, 256, SMEM_BYTES>>>(bias, y, OUT, MT);
}